// round 6
// baseline (speedup 1.0000x reference)
#include <cuda_runtime.h>
#include <cstdint>

#define BATCH 2
#define SEQ 2048
#define DIM 512
#define INNER 512
#define N_HEAD 8
#define HEAD_DIM 64
#define ATT_T 1e-4f
#define SCALE_F 0.125f

typedef unsigned long long ull;

// scratch (allocation-free rule: __device__ globals)
__device__ float g_Q[BATCH * SEQ * INNER];
__device__ float g_K[BATCH * SEQ * INNER];
__device__ float g_V[BATCH * SEQ * INNER];
__device__ float g_O[BATCH * SEQ * INNER];
__device__ float g_P[(size_t)BATCH * N_HEAD * SEQ * SEQ];   // exp(scores), 268MB
__device__ float g_Z[BATCH * N_HEAD * SEQ];

// ---------------- packed f32x2 helpers ---------------------------------
static __device__ __forceinline__ void fma2(ull& d, ull a, ull b) {
    asm("fma.rn.f32x2 %0, %1, %2, %0;" : "+l"(d) : "l"(a), "l"(b));
}
static __device__ __forceinline__ float2 up2(ull v) {
    unsigned lo, hi;
    asm("mov.b64 {%0, %1}, %2;" : "=r"(lo), "=r"(hi) : "l"(v));
    return make_float2(__uint_as_float(lo), __uint_as_float(hi));
}
static __device__ __forceinline__ float psum(ull v) {
    float2 f = up2(v);
    return f.x + f.y;
}

// swizzled float4 store: logical float col c (mult of 4) in `row`, tag t.
// pair p -> slot p^t; the float4 = pairs {c>>1, (c>>1)+1}.
static __device__ __forceinline__ void st_sw4(float* base, int stride_f,
                                              int row, int c, int t, float4 v) {
    int e = ((c >> 1) ^ t) & ~1;
    if (t & 1) { float x = v.x, y = v.y; v.x = v.z; v.y = v.w; v.z = x; v.w = y; }
    *(float4*)&base[row * stride_f + (e << 1)] = v;
}

// ---------------------------------------------------------------------------
// gemm128: C[M,N] = A[M,K] @ B[K,N] (+bias). 512 thr, 128x128 tile, BK=64.
// Reduction-packed FFMA2: both operands natural LDS.64 pairs.
// smem: As[m][k] tag m>>3, Bs[n][k] (transposed) tag n>>2.
// ---------------------------------------------------------------------------
__global__ void __launch_bounds__(512, 1) gemm128(
    const float* __restrict__ A, const float* __restrict__ B,
    const float* __restrict__ bias, float* __restrict__ C,
    int M, int N, int K)
{
    extern __shared__ float sm[];
    float* As = sm;              // 128 x 64
    float* Bs = sm + 128 * 64;   // 128 x 64

    const int tid = threadIdx.x;
    const int tx = tid & 31, ty = tid >> 5;
    const int tx4 = tx << 2, ty8 = ty << 3;
    const int bn = blockIdx.x * 128, bm = blockIdx.y * 128;

    ull acc2[8][4];
    #pragma unroll
    for (int i = 0; i < 8; i++)
        #pragma unroll
        for (int j = 0; j < 4; j++) acc2[i][j] = 0ull;

    for (int kc = 0; kc < K; kc += 64) {
        __syncthreads();
        #pragma unroll
        for (int i = 0; i < 4; i++) {                 // A fill
            int idx = tid + 512 * i;
            int row = idx >> 4;                       // m 0..127
            int c   = (idx & 15) << 2;                // k
            float4 v = *(const float4*)&A[(size_t)(bm + row) * K + kc + c];
            st_sw4(As, 64, row, c, row >> 3, v);
        }
        #pragma unroll
        for (int i = 0; i < 4; i++) {                 // B fill (transpose)
            int idx = tid + 512 * i;
            int k   = idx >> 5;                       // 0..63
            int c   = (idx & 31) << 2;                // n 0..124
            float4 v = *(const float4*)&B[(size_t)(kc + k) * N + bn + c];
            int t = c >> 2, pk = k >> 1;
            int sl = ((pk ^ t) << 1) | (k & 1);
            Bs[(c + 0) * 64 + sl] = v.x; Bs[(c + 1) * 64 + sl] = v.y;
            Bs[(c + 2) * 64 + sl] = v.z; Bs[(c + 3) * 64 + sl] = v.w;
        }
        __syncthreads();

        #pragma unroll 4
        for (int dp = 0; dp < 32; dp++) {
            ull a2[8], b2[4];
            int ao = (dp ^ ty) << 1;
            int bo = (dp ^ tx) << 1;
            #pragma unroll
            for (int i = 0; i < 8; i++) a2[i] = *(const ull*)&As[(ty8 + i) * 64 + ao];
            #pragma unroll
            for (int j = 0; j < 4; j++) b2[j] = *(const ull*)&Bs[(tx4 + j) * 64 + bo];
            #pragma unroll
            for (int i = 0; i < 8; i++)
                #pragma unroll
                for (int j = 0; j < 4; j++)
                    fma2(acc2[i][j], a2[i], b2[j]);
        }
    }

    #pragma unroll
    for (int i = 0; i < 8; i++) {
        int row = bm + ty8 + i, col = bn + tx4;
        float4 o = {psum(acc2[i][0]), psum(acc2[i][1]),
                    psum(acc2[i][2]), psum(acc2[i][3])};
        if (bias) {
            o.x += bias[col]; o.y += bias[col + 1];
            o.z += bias[col + 2]; o.w += bias[col + 3];
        }
        *(float4*)&C[(size_t)row * N + col] = o;
    }
}

// ---------------------------------------------------------------------------
// Pass A: S = Q K^T * scale, P = exp(S) -> gmem, Z = row sums -> gmem.
// No max-subtraction needed: |s| bounded (~18), exp safe in fp32.
// Block = (qt 128, h, b), 512 thr, per-thread 8q x 4k.
// ---------------------------------------------------------------------------
__global__ void __launch_bounds__(512, 1) attn_score()
{
    extern __shared__ float sm[];
    float* Qs = sm;              // 128 x 64, tag q>>3
    float* Ks = sm + 128 * 64;   // 128 x 64, tag k>>2

    const int tid = threadIdx.x;
    const int tx = tid & 31, ty = tid >> 5;
    const int tx4 = tx << 2, ty8 = ty << 3;
    const int qt = blockIdx.x, h = blockIdx.y, b = blockIdx.z;

    const size_t baseQ = ((size_t)b * SEQ + qt * 128) * INNER + h * HEAD_DIM;
    const size_t baseK = ((size_t)b * SEQ) * INNER + h * HEAD_DIM;
    const size_t rowP  = ((size_t)(b * N_HEAD + h) * SEQ + qt * 128);

    #pragma unroll
    for (int i = 0; i < 4; i++) {
        int idx = tid + 512 * i;
        int row = idx >> 4;
        int c   = (idx & 15) << 2;
        float4 v = *(const float4*)&g_Q[baseQ + (size_t)row * INNER + c];
        st_sw4(Qs, 64, row, c, row >> 3, v);
    }

    float l[8];
    #pragma unroll
    for (int i = 0; i < 8; i++) l[i] = 0.f;

    for (int kt = 0; kt < SEQ / 128; kt++) {
        __syncthreads();
        #pragma unroll
        for (int i = 0; i < 4; i++) {
            int idx = tid + 512 * i;
            int row = idx >> 4;
            int c   = (idx & 15) << 2;
            float4 v = *(const float4*)&g_K[baseK + (size_t)(kt * 128 + row) * INNER + c];
            st_sw4(Ks, 64, row, c, row >> 2, v);
        }
        __syncthreads();

        ull acc2[8][4];
        #pragma unroll
        for (int i = 0; i < 8; i++)
            #pragma unroll
            for (int j = 0; j < 4; j++) acc2[i][j] = 0ull;

        #pragma unroll 4
        for (int dp = 0; dp < 32; dp++) {
            ull q2[8], k2[4];
            int qo = (dp ^ ty) << 1;
            int ko = (dp ^ tx) << 1;
            #pragma unroll
            for (int i = 0; i < 8; i++) q2[i] = *(const ull*)&Qs[(ty8 + i) * 64 + qo];
            #pragma unroll
            for (int j = 0; j < 4; j++) k2[j] = *(const ull*)&Ks[(tx4 + j) * 64 + ko];
            #pragma unroll
            for (int i = 0; i < 8; i++)
                #pragma unroll
                for (int j = 0; j < 4; j++)
                    fma2(acc2[i][j], q2[i], k2[j]);
        }

        #pragma unroll
        for (int qi = 0; qi < 8; qi++) {
            float4 p;
            p.x = __expf(psum(acc2[qi][0]) * SCALE_F);
            p.y = __expf(psum(acc2[qi][1]) * SCALE_F);
            p.z = __expf(psum(acc2[qi][2]) * SCALE_F);
            p.w = __expf(psum(acc2[qi][3]) * SCALE_F);
            l[qi] += (p.x + p.y) + (p.z + p.w);
            *(float4*)&g_P[(rowP + ty8 + qi) * SEQ + kt * 128 + tx4] = p;
        }
    }

    #pragma unroll
    for (int qi = 0; qi < 8; qi++) {
        float v = l[qi];
        #pragma unroll
        for (int o = 1; o < 32; o <<= 1)
            v += __shfl_xor_sync(0xffffffffu, v, o);
        if (tx == 0)
            g_Z[(b * N_HEAD + h) * SEQ + qt * 128 + ty8 + qi] = v;
    }
}

// ---------------------------------------------------------------------------
// Pass B: w = relu(P - t*Z) (applied during smem fill, with per-row sums),
// O = (w @ V) / rowsum(w). Block = (qt 128, h, b), 256 thr, 8q x 4d each.
// ---------------------------------------------------------------------------
__global__ void __launch_bounds__(256, 2) attn_pv()
{
    extern __shared__ float sm[];
    float* Ws = sm;                    // 128 x 128, tag q>>3
    float* Vs = Ws + 128 * 128;        // 64 x 128 (V^T), tag d>>2
    float* wsumS = Vs + 64 * 128;      // 128
    float* thrS  = wsumS + 128;        // 128

    const int tid = threadIdx.x;
    const int tx = tid & 15, ty = tid >> 4;
    const int tx4 = tx << 2, ty8 = ty << 3;
    const int qt = blockIdx.x, h = blockIdx.y, b = blockIdx.z;

    const size_t baseV = ((size_t)b * SEQ) * INNER + h * HEAD_DIM;
    const size_t baseO = ((size_t)b * SEQ + qt * 128) * INNER + h * HEAD_DIM;
    const size_t rowP  = ((size_t)(b * N_HEAD + h) * SEQ + qt * 128);
    const int    rowZ  = (b * N_HEAD + h) * SEQ + qt * 128;

    if (tid < 128) {
        thrS[tid] = ATT_T * g_Z[rowZ + tid];
        wsumS[tid] = 0.f;
    }

    ull oacc[8][4];
    #pragma unroll
    for (int i = 0; i < 8; i++)
        #pragma unroll
        for (int j = 0; j < 4; j++) oacc[i][j] = 0ull;

    for (int kt = 0; kt < SEQ / 128; kt++) {
        __syncthreads();
        // fill Ws with w = relu(P - thr); accumulate per-row sums.
        // 16 iters x 256 thr x float4 = 16384 floats = full 128x128 tile.
        // row = 8*i + warp  (unique per (i, warp) -> race-free wsumS update)
        #pragma unroll
        for (int i = 0; i < 16; i++) {
            int idx = tid + 256 * i;
            int row = idx >> 5;                 // q row 0..127; const per warp
            int c   = (idx & 31) << 2;          // k col
            float4 p = *(const float4*)&g_P[(rowP + row) * SEQ + kt * 128 + c];
            float t = thrS[row];
            float4 w;
            w.x = fmaxf(p.x - t, 0.f); w.y = fmaxf(p.y - t, 0.f);
            w.z = fmaxf(p.z - t, 0.f); w.w = fmaxf(p.w - t, 0.f);
            float s = (w.x + w.y) + (w.z + w.w);
            #pragma unroll
            for (int o = 16; o > 0; o >>= 1)
                s += __shfl_xor_sync(0xffffffffu, s, o);
            if ((tid & 31) == 0) wsumS[row] += s;
            st_sw4(Ws, 128, row, c, row >> 3, w);
        }
        // fill Vs (transpose)
        #pragma unroll
        for (int i = 0; i < 8; i++) {
            int idx = tid + 256 * i;
            int row = idx >> 4;                 // k 0..127
            int c   = (idx & 15) << 2;          // d
            float4 v = *(const float4*)&g_V[baseV + (size_t)(kt * 128 + row) * INNER + c];
            int t = c >> 2, pk = row >> 1;
            int sl = ((pk ^ t) << 1) | (row & 1);
            Vs[(c + 0) * 128 + sl] = v.x; Vs[(c + 1) * 128 + sl] = v.y;
            Vs[(c + 2) * 128 + sl] = v.z; Vs[(c + 3) * 128 + sl] = v.w;
        }
        __syncthreads();

        #pragma unroll 4
        for (int kp = 0; kp < 64; kp++) {
            ull w2[8], v2[4];
            int wo = (kp ^ ty) << 1;
            int vo = (kp ^ tx) << 1;
            #pragma unroll
            for (int i = 0; i < 8; i++) w2[i] = *(const ull*)&Ws[(ty8 + i) * 128 + wo];
            #pragma unroll
            for (int j = 0; j < 4; j++) v2[j] = *(const ull*)&Vs[(tx4 + j) * 128 + vo];
            #pragma unroll
            for (int i = 0; i < 8; i++)
                #pragma unroll
                for (int j = 0; j < 4; j++)
                    fma2(oacc[i][j], w2[i], v2[j]);
        }
    }

    #pragma unroll
    for (int qi = 0; qi < 8; qi++) {
        float inv = 1.f / wsumS[ty8 + qi];
        float4 ov = {psum(oacc[qi][0]) * inv, psum(oacc[qi][1]) * inv,
                     psum(oacc[qi][2]) * inv, psum(oacc[qi][3]) * inv};
        *(float4*)&g_O[baseO + (size_t)(ty8 + qi) * INNER + tx4] = ov;
    }
}

// ---------------------------------------------------------------------------
extern "C" void kernel_launch(void* const* d_in, const int* in_sizes, int n_in,
                              void* d_out, int out_size)
{
    const float* fr = (const float*)d_in[0];
    const float* dt = (const float*)d_in[1];
    const float* Wq = (const float*)d_in[2];
    const float* Wk = (const float*)d_in[3];
    const float* Wv = (const float*)d_in[4];
    const float* Wo = (const float*)d_in[5];
    const float* bo = (const float*)d_in[6];
    float* out = (float*)d_out;

    float *pQ, *pK, *pV, *pO;
    cudaGetSymbolAddress((void**)&pQ, g_Q);
    cudaGetSymbolAddress((void**)&pK, g_K);
    cudaGetSymbolAddress((void**)&pV, g_V);
    cudaGetSymbolAddress((void**)&pO, g_O);

    const int M = BATCH * SEQ;   // 4096

    const int smG = 128 * 64 * 2 * (int)sizeof(float);                  // 64KB
    const int smA = 128 * 64 * 2 * (int)sizeof(float);                  // 64KB
    const int smB = (128 * 128 + 64 * 128 + 256) * (int)sizeof(float);  // ~97KB
    cudaFuncSetAttribute(gemm128,    cudaFuncAttributeMaxDynamicSharedMemorySize, smG);
    cudaFuncSetAttribute(attn_score, cudaFuncAttributeMaxDynamicSharedMemorySize, smA);
    cudaFuncSetAttribute(attn_pv,    cudaFuncAttributeMaxDynamicSharedMemorySize, smB);

    dim3 gp(INNER / 128, M / 128);
    gemm128<<<gp, 512, smG>>>(fr, Wq, nullptr, pQ, M, INNER, DIM);
    gemm128<<<gp, 512, smG>>>(dt, Wk, nullptr, pK, M, INNER, DIM);
    gemm128<<<gp, 512, smG>>>(dt, Wv, nullptr, pV, M, INNER, DIM);

    attn_score<<<dim3(SEQ / 128, N_HEAD, BATCH), 512, smA>>>();
    attn_pv<<<dim3(SEQ / 128, N_HEAD, BATCH), 256, smB>>>();

    dim3 go(DIM / 128, M / 128);
    gemm128<<<go, 512, smG>>>(pO, Wo, bo, out, M, DIM, INNER);
}